// round 11
// baseline (speedup 1.0000x reference)
#include <cuda_runtime.h>
#include <cuda_fp16.h>
#include <cstdint>

#define NBATCH 16
#define TLEN   1024
#define DHID   768
#define NCTA   96
#define NSTEP  2048
#define NTHR   256

// ---------------- global scratch (no device allocation allowed) ----------------
__device__ __align__(16) __half g_hbuf[2][NBATCH * DHID];  // h double buffer, fp16 [b][d]
__device__ int g_cnt[NSTEP];                               // per-step arrival counters

__global__ void init_kernel(const float* __restrict__ states) {
    int i = blockIdx.x * blockDim.x + threadIdx.x;
    if (i < NBATCH * DHID) g_hbuf[0][i] = __float2half_rn(states[i]);
    if (i < NSTEP) g_cnt[i] = 0;
}

// ---------------- helpers ----------------
__device__ __forceinline__ float fast_sigmoid(float x) {
    return 1.f / (1.f + __expf(-x));
}
__device__ __forceinline__ float fast_tanh(float x) {
    float ax = fabsf(x);
    float e  = __expf(-2.f * ax);
    float r  = (1.f - e) / (1.f + e);
    return copysignf(r, x);
}
__device__ __forceinline__ uint32_t ldcg_b32(const void* p) {
    uint32_t v;
    asm volatile("ld.global.cg.b32 %0, [%1];" : "=r"(v) : "l"(p));
    return v;
}
__device__ __forceinline__ uint32_t pack_h2(float lo, float hi) {
    __half2 h = __floats2half2_rn(lo, hi);
    return *reinterpret_cast<uint32_t*>(&h);
}
__device__ __forceinline__ void mma16816(float* d, const uint32_t* a, const uint32_t* b) {
    asm volatile(
        "mma.sync.aligned.m16n8k16.row.col.f32.f16.f16.f32 "
        "{%0,%1,%2,%3}, {%4,%5,%6,%7}, {%8,%9}, {%0,%1,%2,%3};"
        : "+f"(d[0]), "+f"(d[1]), "+f"(d[2]), "+f"(d[3])
        : "r"(a[0]), "r"(a[1]), "r"(a[2]), "r"(a[3]), "r"(b[0]), "r"(b[1]));
}

// red[w][l][b]: w in [0,8) warps, l in [0,32) local gate-rows, b padded to 17
#define REDW 544  // 32*17 floats per warp slice

__global__ void __launch_bounds__(NTHR, 1)
lstm_kernel(const float* __restrict__ states,
            const float* __restrict__ Wx0, const float* __restrict__ R0, const float* __restrict__ bias0,
            const float* __restrict__ Wx1, const float* __restrict__ R1, const float* __restrict__ bias1,
            float* __restrict__ out)
{
    __shared__ float red[8 * REDW];

    const int tid  = threadIdx.x;
    const int wid  = tid >> 5;
    const int lane = tid & 31;
    const int gid  = lane >> 2;   // mma group id (row)
    const int tig  = lane & 3;    // mma thread-in-group (col/k)
    const int cta  = blockIdx.x;
    const int kbase = wid * 96;   // this warp's K slice

    // epilogue mapping: t -> (b = t>>3, e_l = t&7); e_global = cta*8 + e_l
    const int eb   = tid >> 3;    // batch index (valid for tid<128)
    const int el   = tid & 7;     // local hidden dim
    const int eg   = cta * 8 + el;

    // register-resident state
    uint32_t areg[2][6][4];       // A fragments: [m-tile][k-tile][reg]
    float    bias[4];
    float    creg = 0.f;

    if (tid < 128) {
        creg = states[NBATCH * DHID + eb * DHID + eg];
    }

    for (int s = 0; s < NSTEP; ++s) {
        const int layer = s >> 10;
        const int t     = s & 1023;
        const float* Wx = layer ? Wx1 : Wx0;

        // ---- per-layer setup: load A fragments (R slice) + bias into registers ----
        if (t == 0) {
            const float* R  = layer ? R1 : R0;
            const float* bi = layer ? bias1 : bias0;
            #pragma unroll
            for (int mt = 0; mt < 2; ++mt) {
                const int r0 = mt * 16 + gid;      // local rows r0, r0+8
                const int r1 = r0 + 8;
                const int g0 = r0 >> 3, e0 = cta * 8 + (r0 & 7);
                const int g1 = r1 >> 3, e1 = cta * 8 + (r1 & 7);
                const float* p0 = R + (size_t)g0 * (DHID * DHID) + e0;
                const float* p1 = R + (size_t)g1 * (DHID * DHID) + e1;
                #pragma unroll
                for (int kt = 0; kt < 6; ++kt) {
                    const int k0 = kbase + kt * 16 + tig * 2;
                    areg[mt][kt][0] = pack_h2(__ldg(p0 + (size_t)(k0    ) * DHID),
                                              __ldg(p0 + (size_t)(k0 + 1) * DHID));
                    areg[mt][kt][1] = pack_h2(__ldg(p1 + (size_t)(k0    ) * DHID),
                                              __ldg(p1 + (size_t)(k0 + 1) * DHID));
                    areg[mt][kt][2] = pack_h2(__ldg(p0 + (size_t)(k0 + 8) * DHID),
                                              __ldg(p0 + (size_t)(k0 + 9) * DHID));
                    areg[mt][kt][3] = pack_h2(__ldg(p1 + (size_t)(k0 + 8) * DHID),
                                              __ldg(p1 + (size_t)(k0 + 9) * DHID));
                }
            }
            if (tid < 128) {
                #pragma unroll
                for (int g = 0; g < 4; ++g)
                    bias[g] = __ldg(bi + g * DHID + eg);
            }
        }

        // ---- Wx prefetch (before the spin: DRAM latency hides behind sync) ----
        float wx[4];
        if (tid < 128) {
            const float* wp = Wx + (size_t)eb * (TLEN * 4 * DHID) + (size_t)t * 3072 + eg;
            #pragma unroll
            for (int g = 0; g < 4; ++g)
                wx[g] = __ldcs(wp + g * DHID);
        }

        // ---- wait for previous step's h broadcast ----
        if (s > 0) {
            if (tid == 0) {
                unsigned v;
                do {
                    asm volatile("ld.acquire.gpu.global.u32 %0, [%1];"
                                 : "=r"(v) : "l"(g_cnt + (s - 1)) : "memory");
                } while (v < NCTA);
            }
            __syncthreads();
        }

        // ---- B fragments straight from global h buffer (L2, coherent) ----
        const __half* hb = g_hbuf[s & 1];
        uint32_t bf[6][2][2];
        #pragma unroll
        for (int kt = 0; kt < 6; ++kt) {
            const int k0 = kbase + kt * 16 + tig * 2;
            #pragma unroll
            for (int nt = 0; nt < 2; ++nt) {
                const __half* hp = hb + (nt * 8 + gid) * DHID + k0;
                bf[kt][nt][0] = ldcg_b32(hp);
                bf[kt][nt][1] = ldcg_b32(hp + 8);
            }
        }

        // ---- MMA: partial D[32,16] over this warp's K slice ----
        float acc[2][2][4];
        #pragma unroll
        for (int mt = 0; mt < 2; ++mt)
            #pragma unroll
            for (int nt = 0; nt < 2; ++nt)
                #pragma unroll
                for (int r = 0; r < 4; ++r)
                    acc[mt][nt][r] = 0.f;
        #pragma unroll
        for (int kt = 0; kt < 6; ++kt)
            #pragma unroll
            for (int mt = 0; mt < 2; ++mt)
                #pragma unroll
                for (int nt = 0; nt < 2; ++nt)
                    mma16816(acc[mt][nt], areg[mt][kt], bf[kt][nt]);

        // ---- write partials to SMEM for cross-warp K reduction ----
        #pragma unroll
        for (int mt = 0; mt < 2; ++mt) {
            const int l0 = mt * 16 + gid;
            #pragma unroll
            for (int nt = 0; nt < 2; ++nt) {
                const int n0 = nt * 8 + tig * 2;
                float* rp = red + wid * REDW;
                rp[(l0    ) * 17 + n0    ] = acc[mt][nt][0];
                rp[(l0    ) * 17 + n0 + 1] = acc[mt][nt][1];
                rp[(l0 + 8) * 17 + n0    ] = acc[mt][nt][2];
                rp[(l0 + 8) * 17 + n0 + 1] = acc[mt][nt][3];
            }
        }
        __syncthreads();

        // ---- epilogue: reduce, activations, cell update, broadcast ----
        if (tid < 128) {
            float gate[4];
            #pragma unroll
            for (int g = 0; g < 4; ++g) {
                float v = wx[g] + bias[g];
                const int li = g * 8 + el;
                #pragma unroll
                for (int w = 0; w < 8; ++w)
                    v += red[w * REDW + li * 17 + eb];
                gate[g] = v;
            }
            const float iv = fast_sigmoid(gate[0]);
            const float fv = fast_sigmoid(gate[1]);
            const float zv = fast_tanh(gate[2]);
            const float ov = fast_sigmoid(gate[3]);
            creg = fv * creg + iv * zv;
            const float hv = ov * fast_tanh(creg);

            // h broadcast for next step
            g_hbuf[(s + 1) & 1][eb * DHID + eg] = __float2half_rn(hv);

            // layer-2 outputs
            if (layer) {
                float* po = out + (size_t)t * 24576 + eb * DHID + eg;
                po[0]     = hv;
                po[12288] = creg;
                if (t == TLEN - 1) {
                    float* pl = out + (size_t)25165824 + eb * DHID + eg;
                    pl[0]             = hv;    // last_h: h
                    pl[12288]         = creg;  // last_h: c
                    pl[24576]         = hv;    // out: h
                    pl[24576 + 12288] = creg;  // out: c
                }
            }
        }
        __syncthreads();
        if (tid == 0) {
            asm volatile("red.release.gpu.global.add.u32 [%0], 1;"
                         :: "l"(g_cnt + s) : "memory");
        }
    }
}

extern "C" void kernel_launch(void* const* d_in, const int* in_sizes, int n_in,
                              void* d_out, int out_size) {
    (void)in_sizes; (void)n_in; (void)out_size;
    const float* states = (const float*)d_in[0];
    const float* Wx0    = (const float*)d_in[1];
    const float* R0     = (const float*)d_in[2];
    const float* b0     = (const float*)d_in[3];
    const float* Wx1    = (const float*)d_in[4];
    const float* R1     = (const float*)d_in[5];
    const float* b1     = (const float*)d_in[6];
    float* out = (float*)d_out;

    init_kernel<<<48, 256>>>(states);
    lstm_kernel<<<NCTA, NTHR>>>(states, Wx0, R0, b0, Wx1, R1, b1, out);
}